// round 2
// baseline (speedup 1.0000x reference)
#include <cuda_runtime.h>
#include <cstdint>

#define NB   8
#define NN   8192
#define NK   2048
#define NSMP 32

// ---------------- device scratch (static; no allocation allowed) ----------------
__device__ float4 g_y0[(size_t)NB * NK * 16 * NSMP];   // (b,k,c4,s) 128 MiB
__device__ float4 g_y1[(size_t)NB * NK * 16 * NSMP];   // 128 MiB
__device__ float  g_mx[(size_t)NB * NK * 128];
__device__ float  g_mn[(size_t)NB * NK * 128];
__device__ int    g_knn[(size_t)NB * NK * NSMP];
__device__ float  g_part[2048 * 16];                   // per-block GN partials
__device__ float  g_ss[NB * 128 * 2];                  // per-(b,c) scale/shift

// =========================== FPS ===========================
__global__ void __launch_bounds__(512) fps_kernel(const float* __restrict__ xyz,
                                                  float* __restrict__ newxyz)
{
    __shared__ float scur[3];
    __shared__ float swmax[16];
    __shared__ float sbmax;
    __shared__ int   sidx;
    const int b = blockIdx.x, tid = threadIdx.x;
    const int lane = tid & 31, warp = tid >> 5;
    const float* X = xyz + (size_t)b * NN * 3;

    float px[16], py[16], pz[16], d[16];
#pragma unroll
    for (int t = 0; t < 16; t++) {
        int i = t * 512 + tid;
        px[t] = X[i * 3 + 0];
        py[t] = X[i * 3 + 1];
        pz[t] = X[i * 3 + 2];
        d[t]  = __int_as_float(0x7f800000);
    }
    if (tid == 0) {
        scur[0] = px[0]; scur[1] = py[0]; scur[2] = pz[0];
        float* o = newxyz + (size_t)b * NK * 3;
        o[0] = px[0]; o[1] = py[0]; o[2] = pz[0];
    }
    __syncthreads();

    const float NEGINF = __int_as_float(0xff800000);
    for (int k = 1; k < NK; k++) {
        float cx = scur[0], cy = scur[1], cz = scur[2];
        float tm = NEGINF;
#pragma unroll
        for (int t = 0; t < 16; t++) {
            // mimic XLA: separate sub/mul/add, no FMA contraction
            float dx = __fsub_rn(px[t], cx);
            float dy = __fsub_rn(py[t], cy);
            float dz = __fsub_rn(pz[t], cz);
            float dist = __fadd_rn(__fadd_rn(__fmul_rn(dx, dx), __fmul_rn(dy, dy)),
                                   __fmul_rn(dz, dz));
            float nd = fminf(d[t], dist);
            d[t] = nd;
            tm = fmaxf(tm, nd);
        }
        float m = tm;
#pragma unroll
        for (int o = 16; o > 0; o >>= 1)
            m = fmaxf(m, __shfl_xor_sync(0xffffffffu, m, o));
        if (lane == 0) swmax[warp] = m;
        __syncthreads();
        if (tid < 32) {
            float v = (tid < 16) ? swmax[tid] : NEGINF;
#pragma unroll
            for (int o = 8; o > 0; o >>= 1)
                v = fmaxf(v, __shfl_xor_sync(0xffffffffu, v, o));
            if (tid == 0) { sbmax = v; sidx = 0x7fffffff; }
        }
        __syncthreads();
        float bmax = sbmax;
        if (tm == bmax) {
            // lowest global index tie-break == jnp.argmax
            for (int t = 0; t < 16; t++) {
                if (d[t] == bmax) { atomicMin(&sidx, t * 512 + tid); break; }
            }
        }
        __syncthreads();
        int sel = sidx;
        if ((sel & 511) == tid) {
            int t = sel >> 9;
            scur[0] = px[t]; scur[1] = py[t]; scur[2] = pz[t];
            float* o = newxyz + ((size_t)b * NK + k) * 3;
            o[0] = px[t]; o[1] = py[t]; o[2] = pz[t];
        }
        __syncthreads();
    }
}

// =========================== kNN (top-32 smallest d2) ===========================
__device__ __forceinline__ unsigned encf(float f)
{
    unsigned u = __float_as_uint(f);
    return u ^ (((unsigned)((int)u >> 31)) | 0x80000000u);
}

__global__ void __launch_bounds__(256) knn_kernel(const float* __restrict__ xyz,
                                                  const float* __restrict__ newxyz)
{
    extern __shared__ float4 pts[];   // 8192 * 16B = 128 KB
    const int b = blockIdx.y, tid = threadIdx.x;
    const int lane = tid & 31, warp = tid >> 5;
    const float* X = xyz + (size_t)b * NN * 3;
    for (int i = tid; i < NN; i += 256) {
        float x = X[i * 3 + 0], y = X[i * 3 + 1], z = X[i * 3 + 2];
        float pp = __fadd_rn(__fadd_rn(__fmul_rn(x, x), __fmul_rn(y, y)), __fmul_rn(z, z));
        pts[i] = make_float4(x, y, z, pp);
    }
    __syncthreads();

    for (int qi = 0; qi < 8; qi++) {
        int q = blockIdx.x * 64 + warp * 8 + qi;
        const float* Q = newxyz + ((size_t)b * NK + q) * 3;
        float qx = Q[0], qy = Q[1], qz = Q[2];
        float qq = __fadd_rn(__fadd_rn(__fmul_rn(qx, qx), __fmul_rn(qy, qy)),
                             __fmul_rn(qz, qz));
        unsigned long long key = ~0ull, tau = ~0ull;
        for (int c0 = 0; c0 < NN; c0 += 128) {
#pragma unroll
            for (int j = 0; j < 4; j++) {
                int pt = c0 + j * 32 + lane;
                float4 p = pts[pt];
                float dot = fmaf(p.z, qz, fmaf(p.y, qy, __fmul_rn(p.x, qx)));
                float d2 = __fsub_rn(__fadd_rn(qq, p.w), __fmul_rn(2.f, dot));
                unsigned long long kk =
                    ((unsigned long long)encf(d2) << 32) | (unsigned)pt;
                unsigned mask = __ballot_sync(0xffffffffu, kk < tau);
                while (mask) {
                    int src = __ffs(mask) - 1; mask &= mask - 1;
                    unsigned long long ck = __shfl_sync(0xffffffffu, kk, src);
                    if (ck < tau) {
                        int ml = __ffs(__ballot_sync(0xffffffffu, key == tau)) - 1;
                        if (lane == ml) key = ck;
                        unsigned long long v = key;
#pragma unroll
                        for (int o = 16; o > 0; o >>= 1) {
                            unsigned long long w = __shfl_xor_sync(0xffffffffu, v, o);
                            v = (w > v) ? w : v;
                        }
                        tau = v;
                    }
                }
            }
        }
        g_knn[((size_t)b * NK + q) * NSMP + lane] = (int)(key & 0xffffffffu);
    }
}

// =========================== Layer 0: gather + 67->16->64 + stats ===========================
__global__ void __launch_bounds__(256) layer0_kernel(
    const float* __restrict__ xyz, const float* __restrict__ feat,
    const float* __restrict__ newxyz,
    const float* __restrict__ w0a, const float* __restrict__ b0a,
    const float* __restrict__ w0b, const float* __restrict__ b0b)
{
    __shared__ __align__(16) float s_wa[67 * 16];  // transposed [c][j]
    __shared__ __align__(16) float s_wb[64 * 16];  // [o][j]
    __shared__ float s_ba[16], s_bb[64];
    __shared__ float s_ws[8 * 8];
    const int tid = threadIdx.x, lane = tid & 31, warp = tid >> 5;
    const int b = blockIdx.y, kb = blockIdx.x;

    for (int i = tid; i < 67 * 16; i += 256) {
        int c = i >> 4, j = i & 15;
        s_wa[i] = w0a[j * 67 + c];
    }
    for (int i = tid; i < 64 * 16; i += 256) s_wb[i] = w0b[i];
    if (tid < 16) s_ba[tid] = b0a[tid];
    if (tid < 64) s_bb[tid] = b0b[tid];
    __syncthreads();

    const int k = kb * 8 + warp;
    const size_t base = (size_t)b * NK + k;
    int nidx = g_knn[base * NSMP + lane];
    const float* Q = newxyz + base * 3;
    float qx = Q[0], qy = Q[1], qz = Q[2];
    const float* P = xyz + ((size_t)b * NN + nidx) * 3;
    float x0 = __fsub_rn(P[0], qx);
    float x1 = __fsub_rn(P[1], qy);
    float x2 = __fsub_rn(P[2], qz);
    const float4* F = (const float4*)feat + ((size_t)b * NN + nidx) * 16;
    float4 f[16];
#pragma unroll
    for (int i = 0; i < 16; i++) f[i] = F[i];

    float h[16];
#pragma unroll
    for (int j = 0; j < 16; j++) h[j] = s_ba[j];

    auto acc = [&](int c, float xc) {
        const float4* w = (const float4*)&s_wa[c * 16];
#pragma unroll
        for (int q4 = 0; q4 < 4; q4++) {
            float4 ww = w[q4];
            h[q4 * 4 + 0] = fmaf(ww.x, xc, h[q4 * 4 + 0]);
            h[q4 * 4 + 1] = fmaf(ww.y, xc, h[q4 * 4 + 1]);
            h[q4 * 4 + 2] = fmaf(ww.z, xc, h[q4 * 4 + 2]);
            h[q4 * 4 + 3] = fmaf(ww.w, xc, h[q4 * 4 + 3]);
        }
    };
    acc(0, x0); acc(1, x1); acc(2, x2);
#pragma unroll
    for (int i = 0; i < 16; i++) {
        acc(3 + i * 4 + 0, f[i].x);
        acc(3 + i * 4 + 1, f[i].y);
        acc(3 + i * 4 + 2, f[i].z);
        acc(3 + i * 4 + 3, f[i].w);
    }

    float y[64];
#pragma unroll
    for (int o = 0; o < 64; o++) {
        const float4* w = (const float4*)&s_wb[o * 16];
        float a = s_bb[o];
#pragma unroll
        for (int q4 = 0; q4 < 4; q4++) {
            float4 ww = w[q4];
            a = fmaf(ww.x, h[q4 * 4 + 0], a);
            a = fmaf(ww.y, h[q4 * 4 + 1], a);
            a = fmaf(ww.z, h[q4 * 4 + 2], a);
            a = fmaf(ww.w, h[q4 * 4 + 3], a);
        }
        y[o] = a;
    }

    float s1[4] = {0, 0, 0, 0}, s2[4] = {0, 0, 0, 0};
#pragma unroll
    for (int o = 0; o < 64; o++) {
        int g = o >> 4;
        s1[g] += y[o];
        s2[g] = fmaf(y[o], y[o], s2[g]);
    }
#pragma unroll
    for (int c4 = 0; c4 < 16; c4++)
        g_y0[(base * 16 + c4) * NSMP + lane] =
            make_float4(y[c4 * 4], y[c4 * 4 + 1], y[c4 * 4 + 2], y[c4 * 4 + 3]);

#pragma unroll
    for (int g = 0; g < 4; g++) {
#pragma unroll
        for (int o = 16; o > 0; o >>= 1) {
            s1[g] += __shfl_xor_sync(0xffffffffu, s1[g], o);
            s2[g] += __shfl_xor_sync(0xffffffffu, s2[g], o);
        }
    }
    if (lane == 0) {
#pragma unroll
        for (int g = 0; g < 4; g++) {
            s_ws[warp * 8 + 2 * g + 0] = s1[g];
            s_ws[warp * 8 + 2 * g + 1] = s2[g];
        }
    }
    __syncthreads();
    if (tid < 8) {
        float v = 0.f;
        for (int w = 0; w < 8; w++) v += s_ws[w * 8 + tid];
        g_part[((size_t)b * 256 + kb) * 16 + tid] = v;
    }
}

// =========================== GN finalize ===========================
__global__ void finalize_kernel(const float* __restrict__ gamma,
                                const float* __restrict__ beta, int C)
{
    const int b = blockIdx.x, tid = threadIdx.x;
    const int g = tid >> 5, lane = tid & 31;
    double s1 = 0.0, s2 = 0.0;
    for (int j = 0; j < 8; j++) {
        const float* p = &g_part[((size_t)b * 256 + lane * 8 + j) * 16];
        s1 += (double)p[g * 2 + 0];
        s2 += (double)p[g * 2 + 1];
    }
#pragma unroll
    for (int o = 16; o > 0; o >>= 1) {
        s1 += __shfl_xor_sync(0xffffffffu, s1, o);
        s2 += __shfl_xor_sync(0xffffffffu, s2, o);
    }
    const double n = 1048576.0;  // (C/G=16)*32*2048 for every layer
    double mu = s1 / n;
    double var = s2 / n - mu * mu;
    double r = 1.0 / sqrt(var + 1e-5);
    if (lane < 16) {
        int c = g * 16 + lane;
        float s = gamma[c] * (float)r;
        float t = beta[c] - (float)mu * s;
        g_ss[((size_t)b * C + c) * 2 + 0] = s;
        g_ss[((size_t)b * C + c) * 2 + 1] = t;
    }
}

// =========================== Layer 1: norm+relu + 64->16->64 + stats ===========================
__global__ void __launch_bounds__(256) layer1_kernel(
    const float* __restrict__ w1a, const float* __restrict__ b1a,
    const float* __restrict__ w1b, const float* __restrict__ b1b)
{
    __shared__ __align__(16) float s_wa[64 * 16];
    __shared__ __align__(16) float s_wb[64 * 16];
    __shared__ float s_ba[16], s_bb[64], s_sst[128];
    __shared__ float s_ws[8 * 8];
    const int tid = threadIdx.x, lane = tid & 31, warp = tid >> 5;
    const int b = blockIdx.y, kb = blockIdx.x;

    for (int i = tid; i < 64 * 16; i += 256) {
        int c = i >> 4, j = i & 15;
        s_wa[i] = w1a[j * 64 + c];
        s_wb[i] = w1b[i];
    }
    if (tid < 16) s_ba[tid] = b1a[tid];
    if (tid < 64) s_bb[tid] = b1b[tid];
    if (tid < 128) s_sst[tid] = g_ss[(size_t)b * 128 + tid];
    __syncthreads();

    const int k = kb * 8 + warp;
    const size_t base = (size_t)b * NK + k;

    float h[16];
#pragma unroll
    for (int j = 0; j < 16; j++) h[j] = s_ba[j];

#pragma unroll
    for (int i = 0; i < 16; i++) {
        float4 f = g_y0[(base * 16 + i) * NSMP + lane];
        float vv[4] = {f.x, f.y, f.z, f.w};
#pragma unroll
        for (int sub = 0; sub < 4; sub++) {
            int c = i * 4 + sub;
            float xc = fmaxf(fmaf(vv[sub], s_sst[2 * c], s_sst[2 * c + 1]), 0.f);
            const float4* w = (const float4*)&s_wa[c * 16];
#pragma unroll
            for (int q4 = 0; q4 < 4; q4++) {
                float4 ww = w[q4];
                h[q4 * 4 + 0] = fmaf(ww.x, xc, h[q4 * 4 + 0]);
                h[q4 * 4 + 1] = fmaf(ww.y, xc, h[q4 * 4 + 1]);
                h[q4 * 4 + 2] = fmaf(ww.z, xc, h[q4 * 4 + 2]);
                h[q4 * 4 + 3] = fmaf(ww.w, xc, h[q4 * 4 + 3]);
            }
        }
    }

    float y[64];
#pragma unroll
    for (int o = 0; o < 64; o++) {
        const float4* w = (const float4*)&s_wb[o * 16];
        float a = s_bb[o];
#pragma unroll
        for (int q4 = 0; q4 < 4; q4++) {
            float4 ww = w[q4];
            a = fmaf(ww.x, h[q4 * 4 + 0], a);
            a = fmaf(ww.y, h[q4 * 4 + 1], a);
            a = fmaf(ww.z, h[q4 * 4 + 2], a);
            a = fmaf(ww.w, h[q4 * 4 + 3], a);
        }
        y[o] = a;
    }

    float s1[4] = {0, 0, 0, 0}, s2[4] = {0, 0, 0, 0};
#pragma unroll
    for (int o = 0; o < 64; o++) {
        int g = o >> 4;
        s1[g] += y[o];
        s2[g] = fmaf(y[o], y[o], s2[g]);
    }
#pragma unroll
    for (int c4 = 0; c4 < 16; c4++)
        g_y1[(base * 16 + c4) * NSMP + lane] =
            make_float4(y[c4 * 4], y[c4 * 4 + 1], y[c4 * 4 + 2], y[c4 * 4 + 3]);

#pragma unroll
    for (int g = 0; g < 4; g++) {
#pragma unroll
        for (int o = 16; o > 0; o >>= 1) {
            s1[g] += __shfl_xor_sync(0xffffffffu, s1[g], o);
            s2[g] += __shfl_xor_sync(0xffffffffu, s2[g], o);
        }
    }
    if (lane == 0) {
#pragma unroll
        for (int g = 0; g < 4; g++) {
            s_ws[warp * 8 + 2 * g + 0] = s1[g];
            s_ws[warp * 8 + 2 * g + 1] = s2[g];
        }
    }
    __syncthreads();
    if (tid < 8) {
        float v = 0.f;
        for (int w = 0; w < 8; w++) v += s_ws[w * 8 + tid];
        g_part[((size_t)b * 256 + kb) * 16 + tid] = v;
    }
}

// =========================== Layer 2: norm+relu + 64->32->128 + stats + S-max/min ===========================
__global__ void __launch_bounds__(256) layer2_kernel(
    const float* __restrict__ w2a, const float* __restrict__ b2a,
    const float* __restrict__ w2b, const float* __restrict__ b2b)
{
    extern __shared__ float sm[];
    float* s_wa  = sm;            // 64*32 transposed [c][j]
    float* s_wb  = s_wa + 2048;   // 128*32 [o][j]
    float* s_ba  = s_wb + 4096;   // 32
    float* s_bb  = s_ba + 32;     // 128
    float* s_sst = s_bb + 128;    // 128
    float* s_ws  = s_sst + 128;   // 8*16
    float* s_tr  = s_ws + 128;    // 8*32*33
    const int tid = threadIdx.x, lane = tid & 31, warp = tid >> 5;
    const int b = blockIdx.y, kb = blockIdx.x;

    for (int i = tid; i < 64 * 32; i += 256) {
        int c = i >> 5, j = i & 31;
        s_wa[i] = w2a[j * 64 + c];
    }
    for (int i = tid; i < 128 * 32; i += 256) s_wb[i] = w2b[i];
    if (tid < 32) s_ba[tid] = b2a[tid];
    if (tid < 128) s_bb[tid] = b2b[tid];
    if (tid < 128) s_sst[tid] = g_ss[(size_t)b * 128 + tid];
    __syncthreads();

    const int k = kb * 8 + warp;
    const size_t base = (size_t)b * NK + k;

    float h[32];
#pragma unroll
    for (int j = 0; j < 32; j++) h[j] = s_ba[j];

#pragma unroll
    for (int i = 0; i < 16; i++) {
        float4 f = g_y1[(base * 16 + i) * NSMP + lane];
        float vv[4] = {f.x, f.y, f.z, f.w};
#pragma unroll
        for (int sub = 0; sub < 4; sub++) {
            int c = i * 4 + sub;
            float xc = fmaxf(fmaf(vv[sub], s_sst[2 * c], s_sst[2 * c + 1]), 0.f);
            const float4* w = (const float4*)&s_wa[c * 32];
#pragma unroll
            for (int q4 = 0; q4 < 8; q4++) {
                float4 ww = w[q4];
                h[q4 * 4 + 0] = fmaf(ww.x, xc, h[q4 * 4 + 0]);
                h[q4 * 4 + 1] = fmaf(ww.y, xc, h[q4 * 4 + 1]);
                h[q4 * 4 + 2] = fmaf(ww.z, xc, h[q4 * 4 + 2]);
                h[q4 * 4 + 3] = fmaf(ww.w, xc, h[q4 * 4 + 3]);
            }
        }
    }

    float s1[8] = {0, 0, 0, 0, 0, 0, 0, 0}, s2[8] = {0, 0, 0, 0, 0, 0, 0, 0};
    float* tr = s_tr + warp * (32 * 33);

    for (int ch = 0; ch < 4; ch++) {
        float yv[32];
#pragma unroll
        for (int i = 0; i < 32; i++) {
            int o = ch * 32 + i;
            const float4* w = (const float4*)&s_wb[o * 32];
            float a = s_bb[o];
#pragma unroll
            for (int q4 = 0; q4 < 8; q4++) {
                float4 ww = w[q4];
                a = fmaf(ww.x, h[q4 * 4 + 0], a);
                a = fmaf(ww.y, h[q4 * 4 + 1], a);
                a = fmaf(ww.z, h[q4 * 4 + 2], a);
                a = fmaf(ww.w, h[q4 * 4 + 3], a);
            }
            yv[i] = a;
            int g = o >> 4;
            s1[g] += a;
            s2[g] = fmaf(a, a, s2[g]);
        }
        __syncwarp();
#pragma unroll
        for (int i = 0; i < 32; i++) tr[lane * 33 + i] = yv[i];
        __syncwarp();
        float mx = tr[lane], mn = mx;
#pragma unroll
        for (int s = 1; s < 32; s++) {
            float v = tr[s * 33 + lane];
            mx = fmaxf(mx, v);
            mn = fminf(mn, v);
        }
        g_mx[base * 128 + ch * 32 + lane] = mx;
        g_mn[base * 128 + ch * 32 + lane] = mn;
        __syncwarp();
    }

#pragma unroll
    for (int g = 0; g < 8; g++) {
#pragma unroll
        for (int o = 16; o > 0; o >>= 1) {
            s1[g] += __shfl_xor_sync(0xffffffffu, s1[g], o);
            s2[g] += __shfl_xor_sync(0xffffffffu, s2[g], o);
        }
    }
    if (lane == 0) {
#pragma unroll
        for (int g = 0; g < 8; g++) {
            s_ws[warp * 16 + 2 * g + 0] = s1[g];
            s_ws[warp * 16 + 2 * g + 1] = s2[g];
        }
    }
    __syncthreads();
    if (tid < 16) {
        float v = 0.f;
        for (int w = 0; w < 8; w++) v += s_ws[w * 16 + tid];
        g_part[((size_t)b * 256 + kb) * 16 + tid] = v;
    }
}

// =========================== Final: apply GN+ReLU to extremum ===========================
__global__ void __launch_bounds__(256) final_kernel(float* __restrict__ out)
{
    int e = blockIdx.x * 256 + threadIdx.x;           // 0 .. B*K*128/4-1
    int c4 = e & 31;
    int bk = e >> 5;
    int b = bk >> 11;
    int c = c4 * 4;
    float4 mx = ((const float4*)g_mx)[e];
    float4 mn = ((const float4*)g_mn)[e];
    const float4* S = (const float4*)&g_ss[((size_t)b * 128 + c) * 2];
    float4 s0 = S[0], s1 = S[1];
    float4 o;
    o.x = fmaxf(fmaf(s0.x, (s0.x >= 0.f ? mx.x : mn.x), s0.y), 0.f);
    o.y = fmaxf(fmaf(s0.z, (s0.z >= 0.f ? mx.y : mn.y), s0.w), 0.f);
    o.z = fmaxf(fmaf(s1.x, (s1.x >= 0.f ? mx.z : mn.z), s1.y), 0.f);
    o.w = fmaxf(fmaf(s1.z, (s1.z >= 0.f ? mx.w : mn.w), s1.w), 0.f);
    ((float4*)(out + (size_t)NB * NK * 3))[e] = o;
}

// =========================== launch ===========================
extern "C" void kernel_launch(void* const* d_in, const int* in_sizes, int n_in,
                              void* d_out, int out_size)
{
    const float* xyz  = (const float*)d_in[0];
    const float* feat = (const float*)d_in[1];
    const float* w0a = (const float*)d_in[2];
    const float* b0a = (const float*)d_in[3];
    const float* w0b = (const float*)d_in[4];
    const float* b0b = (const float*)d_in[5];
    const float* g0  = (const float*)d_in[6];
    const float* be0 = (const float*)d_in[7];
    const float* w1a = (const float*)d_in[8];
    const float* b1a = (const float*)d_in[9];
    const float* w1b = (const float*)d_in[10];
    const float* b1b = (const float*)d_in[11];
    const float* g1  = (const float*)d_in[12];
    const float* be1 = (const float*)d_in[13];
    const float* w2a = (const float*)d_in[14];
    const float* b2a = (const float*)d_in[15];
    const float* w2b = (const float*)d_in[16];
    const float* b2b = (const float*)d_in[17];
    const float* g2  = (const float*)d_in[18];
    const float* be2 = (const float*)d_in[19];
    float* out = (float*)d_out;

    cudaFuncSetAttribute(knn_kernel, cudaFuncAttributeMaxDynamicSharedMemorySize, 131072);
    cudaFuncSetAttribute(layer2_kernel, cudaFuncAttributeMaxDynamicSharedMemorySize, 65536);

    fps_kernel<<<NB, 512>>>(xyz, out);
    knn_kernel<<<dim3(32, NB), 256, 131072>>>(xyz, out);
    layer0_kernel<<<dim3(256, NB), 256>>>(xyz, feat, out, w0a, b0a, w0b, b0b);
    finalize_kernel<<<NB, 128>>>(g0, be0, 64);
    layer1_kernel<<<dim3(256, NB), 256>>>(w1a, b1a, w1b, b1b);
    finalize_kernel<<<NB, 128>>>(g1, be1, 64);
    layer2_kernel<<<dim3(256, NB), 256, 61440>>>(w2a, b2a, w2b, b2b);
    finalize_kernel<<<NB, 256>>>(g2, be2, 128);
    final_kernel<<<2048, 256>>>(out);
}

// round 3
// speedup vs baseline: 1.0926x; 1.0926x over previous
#include <cuda_runtime.h>
#include <cstdint>

#define NB   8
#define NN   8192
#define NK   2048
#define NSMP 32

// ---------------- device scratch (static; no allocation allowed) ----------------
__device__ float4 g_y0[(size_t)NB * NK * 16 * NSMP];   // (b,k,c4,s) 128 MiB
__device__ float4 g_y1[(size_t)NB * NK * 16 * NSMP];   // 128 MiB
__device__ float  g_mx[(size_t)NB * NK * 128];
__device__ float  g_mn[(size_t)NB * NK * 128];
__device__ int    g_knn[(size_t)NB * NK * NSMP];
__device__ float  g_part[2048 * 16];                   // per-block GN partials
__device__ float  g_ss[NB * 128 * 2];                  // per-(b,c) scale/shift

// ---------------- f32x2 packed helpers (bit-exact per-element .rn) ----------------
__device__ __forceinline__ unsigned long long pk2(float lo, float hi)
{
    unsigned long long r;
    asm("mov.b64 %0, {%1, %2};" : "=l"(r) : "f"(lo), "f"(hi));
    return r;
}
__device__ __forceinline__ void upk2(unsigned long long v, float& lo, float& hi)
{
    asm("mov.b64 {%0, %1}, %2;" : "=f"(lo), "=f"(hi) : "l"(v));
}
__device__ __forceinline__ unsigned long long addx2(unsigned long long a, unsigned long long b)
{
    unsigned long long r;
    asm("add.rn.f32x2 %0, %1, %2;" : "=l"(r) : "l"(a), "l"(b));
    return r;
}
__device__ __forceinline__ unsigned long long mulx2(unsigned long long a, unsigned long long b)
{
    unsigned long long r;
    asm("mul.rn.f32x2 %0, %1, %2;" : "=l"(r) : "l"(a), "l"(b));
    return r;
}

// =========================== FPS ===========================
// one CTA per batch; 512 threads; 16 points/thread packed as 8 f32x2 pairs.
// Iteration: packed distance update (bit-exact vs scalar sub/mul/add),
// scalar min + argmax tracking, redux.sync + packed-key 2-barrier reduction.
__global__ void __launch_bounds__(512) fps_kernel(const float* __restrict__ xyz,
                                                  float* __restrict__ newxyz)
{
    extern __shared__ float4 spts[];                 // 8192 * 16B = 128 KB
    __shared__ unsigned long long swk[16];
    __shared__ float4 scur4;
    const int b = blockIdx.x, tid = threadIdx.x;
    const int lane = tid & 31, warp = tid >> 5;
    const float* X = xyz + (size_t)b * NN * 3;

    // load 16 points/thread; slot s -> global index s*512+tid (ascending in s)
    unsigned long long pX[8], pY[8], pZ[8];
    float d[16];
#pragma unroll
    for (int j = 0; j < 8; j++) {
        int i0 = (2 * j) * 512 + tid;
        int i1 = (2 * j + 1) * 512 + tid;
        float x0 = X[i0 * 3 + 0], y0 = X[i0 * 3 + 1], z0 = X[i0 * 3 + 2];
        float x1 = X[i1 * 3 + 0], y1 = X[i1 * 3 + 1], z1 = X[i1 * 3 + 2];
        spts[i0] = make_float4(x0, y0, z0, 0.f);
        spts[i1] = make_float4(x1, y1, z1, 0.f);
        pX[j] = pk2(x0, x1); pY[j] = pk2(y0, y1); pZ[j] = pk2(z0, z1);
        d[2 * j] = __int_as_float(0x7f800000);
        d[2 * j + 1] = __int_as_float(0x7f800000);
    }
    __syncthreads();
    if (tid == 0) {
        float4 p = spts[0];
        scur4 = p;
        float* o = newxyz + (size_t)b * NK * 3;
        o[0] = p.x; o[1] = p.y; o[2] = p.z;
    }
    __syncthreads();

    const float NEGINF = __int_as_float(0xff800000);
    for (int k = 1; k < NK; k++) {
        float4 c = scur4;
        unsigned long long ncx = pk2(-c.x, -c.x);
        unsigned long long ncy = pk2(-c.y, -c.y);
        unsigned long long ncz = pk2(-c.z, -c.z);
        float tm = NEGINF; int ti = 0;
#pragma unroll
        for (int j = 0; j < 8; j++) {
            // bit-exact: dx = x + (-cx); s = (dx*dx + dy*dy) + dz*dz, all .rn
            unsigned long long dx = addx2(pX[j], ncx);
            unsigned long long dy = addx2(pY[j], ncy);
            unsigned long long dz = addx2(pZ[j], ncz);
            unsigned long long s =
                addx2(addx2(mulx2(dx, dx), mulx2(dy, dy)), mulx2(dz, dz));
            float d0, d1; upk2(s, d0, d1);
            float nd0 = fminf(d[2 * j], d0);
            float nd1 = fminf(d[2 * j + 1], d1);
            d[2 * j] = nd0; d[2 * j + 1] = nd1;
            // strict > keeps lowest slot (= lowest global index) on ties
            if (nd0 > tm) { tm = nd0; ti = 2 * j; }
            if (nd1 > tm) { tm = nd1; ti = 2 * j + 1; }
        }
        // d >= 0 always here, so float bits are order-monotonic
        unsigned enc = __float_as_uint(tm);
        unsigned wmax = __reduce_max_sync(0xffffffffu, enc);
        unsigned ball = __ballot_sync(0xffffffffu, enc == wmax);
        unsigned long long key;
        if (__popc(ball) == 1) {
            int src = __ffs(ball) - 1;
            int g = __shfl_sync(0xffffffffu, ti * 512 + tid, src);
            key = ((unsigned long long)wmax << 32) | (unsigned)(~g);
        } else {
            int g = (enc == wmax) ? (ti * 512 + tid) : 0x7fffffff;
#pragma unroll
            for (int o = 16; o > 0; o >>= 1)
                g = min(g, __shfl_xor_sync(0xffffffffu, g, o));
            key = ((unsigned long long)wmax << 32) | (unsigned)(~g);
        }
        if (lane == 0) swk[warp] = key;
        __syncthreads();
        if (warp == 0) {
            unsigned long long v = (lane < 16) ? swk[lane] : 0ull;
#pragma unroll
            for (int o = 8; o > 0; o >>= 1) {
                unsigned long long w = __shfl_xor_sync(0xffffffffu, v, o);
                v = (w > v) ? w : v;
            }
            if (lane == 0) {
                int sel = (int)(~(unsigned)v);
                float4 p = spts[sel];
                scur4 = p;
                float* o3 = newxyz + ((size_t)b * NK + k) * 3;
                o3[0] = p.x; o3[1] = p.y; o3[2] = p.z;
            }
        }
        __syncthreads();
    }
}

// =========================== kNN (top-32 smallest d2) ===========================
__device__ __forceinline__ unsigned encf(float f)
{
    unsigned u = __float_as_uint(f);
    return u ^ (((unsigned)((int)u >> 31)) | 0x80000000u);
}

__global__ void __launch_bounds__(256) knn_kernel(const float* __restrict__ xyz,
                                                  const float* __restrict__ newxyz)
{
    extern __shared__ float4 pts[];   // 8192 * 16B = 128 KB
    const int b = blockIdx.y, tid = threadIdx.x;
    const int lane = tid & 31, warp = tid >> 5;
    const float* X = xyz + (size_t)b * NN * 3;
    for (int i = tid; i < NN; i += 256) {
        float x = X[i * 3 + 0], y = X[i * 3 + 1], z = X[i * 3 + 2];
        float pp = __fadd_rn(__fadd_rn(__fmul_rn(x, x), __fmul_rn(y, y)), __fmul_rn(z, z));
        pts[i] = make_float4(x, y, z, pp);
    }
    __syncthreads();

    for (int qi = 0; qi < 8; qi++) {
        int q = blockIdx.x * 64 + warp * 8 + qi;
        const float* Q = newxyz + ((size_t)b * NK + q) * 3;
        float qx = Q[0], qy = Q[1], qz = Q[2];
        float qq = __fadd_rn(__fadd_rn(__fmul_rn(qx, qx), __fmul_rn(qy, qy)),
                             __fmul_rn(qz, qz));
        unsigned long long key = ~0ull, tau = ~0ull;
        for (int c0 = 0; c0 < NN; c0 += 128) {
#pragma unroll
            for (int j = 0; j < 4; j++) {
                int pt = c0 + j * 32 + lane;
                float4 p = pts[pt];
                float dot = fmaf(p.z, qz, fmaf(p.y, qy, __fmul_rn(p.x, qx)));
                float d2 = __fsub_rn(__fadd_rn(qq, p.w), __fmul_rn(2.f, dot));
                unsigned long long kk =
                    ((unsigned long long)encf(d2) << 32) | (unsigned)pt;
                unsigned mask = __ballot_sync(0xffffffffu, kk < tau);
                while (mask) {
                    int src = __ffs(mask) - 1; mask &= mask - 1;
                    unsigned long long ck = __shfl_sync(0xffffffffu, kk, src);
                    if (ck < tau) {
                        int ml = __ffs(__ballot_sync(0xffffffffu, key == tau)) - 1;
                        if (lane == ml) key = ck;
                        unsigned long long v = key;
#pragma unroll
                        for (int o = 16; o > 0; o >>= 1) {
                            unsigned long long w = __shfl_xor_sync(0xffffffffu, v, o);
                            v = (w > v) ? w : v;
                        }
                        tau = v;
                    }
                }
            }
        }
        g_knn[((size_t)b * NK + q) * NSMP + lane] = (int)(key & 0xffffffffu);
    }
}

// =========================== Layer 0: gather + 67->16->64 + stats ===========================
__global__ void __launch_bounds__(256) layer0_kernel(
    const float* __restrict__ xyz, const float* __restrict__ feat,
    const float* __restrict__ newxyz,
    const float* __restrict__ w0a, const float* __restrict__ b0a,
    const float* __restrict__ w0b, const float* __restrict__ b0b)
{
    __shared__ __align__(16) float s_wa[67 * 16];  // transposed [c][j]
    __shared__ __align__(16) float s_wb[64 * 16];  // [o][j]
    __shared__ float s_ba[16], s_bb[64];
    __shared__ float s_ws[8 * 8];
    const int tid = threadIdx.x, lane = tid & 31, warp = tid >> 5;
    const int b = blockIdx.y, kb = blockIdx.x;

    for (int i = tid; i < 67 * 16; i += 256) {
        int c = i >> 4, j = i & 15;
        s_wa[i] = w0a[j * 67 + c];
    }
    for (int i = tid; i < 64 * 16; i += 256) s_wb[i] = w0b[i];
    if (tid < 16) s_ba[tid] = b0a[tid];
    if (tid < 64) s_bb[tid] = b0b[tid];
    __syncthreads();

    const int k = kb * 8 + warp;
    const size_t base = (size_t)b * NK + k;
    int nidx = g_knn[base * NSMP + lane];
    const float* Q = newxyz + base * 3;
    float qx = Q[0], qy = Q[1], qz = Q[2];
    const float* P = xyz + ((size_t)b * NN + nidx) * 3;
    float x0 = __fsub_rn(P[0], qx);
    float x1 = __fsub_rn(P[1], qy);
    float x2 = __fsub_rn(P[2], qz);
    const float4* F = (const float4*)feat + ((size_t)b * NN + nidx) * 16;
    float4 f[16];
#pragma unroll
    for (int i = 0; i < 16; i++) f[i] = F[i];

    float h[16];
#pragma unroll
    for (int j = 0; j < 16; j++) h[j] = s_ba[j];

    auto acc = [&](int c, float xc) {
        const float4* w = (const float4*)&s_wa[c * 16];
#pragma unroll
        for (int q4 = 0; q4 < 4; q4++) {
            float4 ww = w[q4];
            h[q4 * 4 + 0] = fmaf(ww.x, xc, h[q4 * 4 + 0]);
            h[q4 * 4 + 1] = fmaf(ww.y, xc, h[q4 * 4 + 1]);
            h[q4 * 4 + 2] = fmaf(ww.z, xc, h[q4 * 4 + 2]);
            h[q4 * 4 + 3] = fmaf(ww.w, xc, h[q4 * 4 + 3]);
        }
    };
    acc(0, x0); acc(1, x1); acc(2, x2);
#pragma unroll
    for (int i = 0; i < 16; i++) {
        acc(3 + i * 4 + 0, f[i].x);
        acc(3 + i * 4 + 1, f[i].y);
        acc(3 + i * 4 + 2, f[i].z);
        acc(3 + i * 4 + 3, f[i].w);
    }

    float y[64];
#pragma unroll
    for (int o = 0; o < 64; o++) {
        const float4* w = (const float4*)&s_wb[o * 16];
        float a = s_bb[o];
#pragma unroll
        for (int q4 = 0; q4 < 4; q4++) {
            float4 ww = w[q4];
            a = fmaf(ww.x, h[q4 * 4 + 0], a);
            a = fmaf(ww.y, h[q4 * 4 + 1], a);
            a = fmaf(ww.z, h[q4 * 4 + 2], a);
            a = fmaf(ww.w, h[q4 * 4 + 3], a);
        }
        y[o] = a;
    }

    float s1[4] = {0, 0, 0, 0}, s2[4] = {0, 0, 0, 0};
#pragma unroll
    for (int o = 0; o < 64; o++) {
        int g = o >> 4;
        s1[g] += y[o];
        s2[g] = fmaf(y[o], y[o], s2[g]);
    }
#pragma unroll
    for (int c4 = 0; c4 < 16; c4++)
        g_y0[(base * 16 + c4) * NSMP + lane] =
            make_float4(y[c4 * 4], y[c4 * 4 + 1], y[c4 * 4 + 2], y[c4 * 4 + 3]);

#pragma unroll
    for (int g = 0; g < 4; g++) {
#pragma unroll
        for (int o = 16; o > 0; o >>= 1) {
            s1[g] += __shfl_xor_sync(0xffffffffu, s1[g], o);
            s2[g] += __shfl_xor_sync(0xffffffffu, s2[g], o);
        }
    }
    if (lane == 0) {
#pragma unroll
        for (int g = 0; g < 4; g++) {
            s_ws[warp * 8 + 2 * g + 0] = s1[g];
            s_ws[warp * 8 + 2 * g + 1] = s2[g];
        }
    }
    __syncthreads();
    if (tid < 8) {
        float v = 0.f;
        for (int w = 0; w < 8; w++) v += s_ws[w * 8 + tid];
        g_part[((size_t)b * 256 + kb) * 16 + tid] = v;
    }
}

// =========================== GN finalize ===========================
__global__ void finalize_kernel(const float* __restrict__ gamma,
                                const float* __restrict__ beta, int C)
{
    const int b = blockIdx.x, tid = threadIdx.x;
    const int g = tid >> 5, lane = tid & 31;
    double s1 = 0.0, s2 = 0.0;
    for (int j = 0; j < 8; j++) {
        const float* p = &g_part[((size_t)b * 256 + lane * 8 + j) * 16];
        s1 += (double)p[g * 2 + 0];
        s2 += (double)p[g * 2 + 1];
    }
#pragma unroll
    for (int o = 16; o > 0; o >>= 1) {
        s1 += __shfl_xor_sync(0xffffffffu, s1, o);
        s2 += __shfl_xor_sync(0xffffffffu, s2, o);
    }
    const double n = 1048576.0;  // (C/G=16)*32*2048 for every layer
    double mu = s1 / n;
    double var = s2 / n - mu * mu;
    double r = 1.0 / sqrt(var + 1e-5);
    if (lane < 16) {
        int c = g * 16 + lane;
        float s = gamma[c] * (float)r;
        float t = beta[c] - (float)mu * s;
        g_ss[((size_t)b * C + c) * 2 + 0] = s;
        g_ss[((size_t)b * C + c) * 2 + 1] = t;
    }
}

// =========================== Layer 1: norm+relu + 64->16->64 + stats ===========================
__global__ void __launch_bounds__(256) layer1_kernel(
    const float* __restrict__ w1a, const float* __restrict__ b1a,
    const float* __restrict__ w1b, const float* __restrict__ b1b)
{
    __shared__ __align__(16) float s_wa[64 * 16];
    __shared__ __align__(16) float s_wb[64 * 16];
    __shared__ float s_ba[16], s_bb[64], s_sst[128];
    __shared__ float s_ws[8 * 8];
    const int tid = threadIdx.x, lane = tid & 31, warp = tid >> 5;
    const int b = blockIdx.y, kb = blockIdx.x;

    for (int i = tid; i < 64 * 16; i += 256) {
        int c = i >> 4, j = i & 15;
        s_wa[i] = w1a[j * 64 + c];
        s_wb[i] = w1b[i];
    }
    if (tid < 16) s_ba[tid] = b1a[tid];
    if (tid < 64) s_bb[tid] = b1b[tid];
    if (tid < 128) s_sst[tid] = g_ss[(size_t)b * 128 + tid];
    __syncthreads();

    const int k = kb * 8 + warp;
    const size_t base = (size_t)b * NK + k;

    float h[16];
#pragma unroll
    for (int j = 0; j < 16; j++) h[j] = s_ba[j];

#pragma unroll
    for (int i = 0; i < 16; i++) {
        float4 f = g_y0[(base * 16 + i) * NSMP + lane];
        float vv[4] = {f.x, f.y, f.z, f.w};
#pragma unroll
        for (int sub = 0; sub < 4; sub++) {
            int c = i * 4 + sub;
            float xc = fmaxf(fmaf(vv[sub], s_sst[2 * c], s_sst[2 * c + 1]), 0.f);
            const float4* w = (const float4*)&s_wa[c * 16];
#pragma unroll
            for (int q4 = 0; q4 < 4; q4++) {
                float4 ww = w[q4];
                h[q4 * 4 + 0] = fmaf(ww.x, xc, h[q4 * 4 + 0]);
                h[q4 * 4 + 1] = fmaf(ww.y, xc, h[q4 * 4 + 1]);
                h[q4 * 4 + 2] = fmaf(ww.z, xc, h[q4 * 4 + 2]);
                h[q4 * 4 + 3] = fmaf(ww.w, xc, h[q4 * 4 + 3]);
            }
        }
    }

    float y[64];
#pragma unroll
    for (int o = 0; o < 64; o++) {
        const float4* w = (const float4*)&s_wb[o * 16];
        float a = s_bb[o];
#pragma unroll
        for (int q4 = 0; q4 < 4; q4++) {
            float4 ww = w[q4];
            a = fmaf(ww.x, h[q4 * 4 + 0], a);
            a = fmaf(ww.y, h[q4 * 4 + 1], a);
            a = fmaf(ww.z, h[q4 * 4 + 2], a);
            a = fmaf(ww.w, h[q4 * 4 + 3], a);
        }
        y[o] = a;
    }

    float s1[4] = {0, 0, 0, 0}, s2[4] = {0, 0, 0, 0};
#pragma unroll
    for (int o = 0; o < 64; o++) {
        int g = o >> 4;
        s1[g] += y[o];
        s2[g] = fmaf(y[o], y[o], s2[g]);
    }
#pragma unroll
    for (int c4 = 0; c4 < 16; c4++)
        g_y1[(base * 16 + c4) * NSMP + lane] =
            make_float4(y[c4 * 4], y[c4 * 4 + 1], y[c4 * 4 + 2], y[c4 * 4 + 3]);

#pragma unroll
    for (int g = 0; g < 4; g++) {
#pragma unroll
        for (int o = 16; o > 0; o >>= 1) {
            s1[g] += __shfl_xor_sync(0xffffffffu, s1[g], o);
            s2[g] += __shfl_xor_sync(0xffffffffu, s2[g], o);
        }
    }
    if (lane == 0) {
#pragma unroll
        for (int g = 0; g < 4; g++) {
            s_ws[warp * 8 + 2 * g + 0] = s1[g];
            s_ws[warp * 8 + 2 * g + 1] = s2[g];
        }
    }
    __syncthreads();
    if (tid < 8) {
        float v = 0.f;
        for (int w = 0; w < 8; w++) v += s_ws[w * 8 + tid];
        g_part[((size_t)b * 256 + kb) * 16 + tid] = v;
    }
}

// =========================== Layer 2: norm+relu + 64->32->128 + stats + S-max/min ===========================
__global__ void __launch_bounds__(256) layer2_kernel(
    const float* __restrict__ w2a, const float* __restrict__ b2a,
    const float* __restrict__ w2b, const float* __restrict__ b2b)
{
    extern __shared__ float sm[];
    float* s_wa  = sm;            // 64*32 transposed [c][j]
    float* s_wb  = s_wa + 2048;   // 128*32 [o][j]
    float* s_ba  = s_wb + 4096;   // 32
    float* s_bb  = s_ba + 32;     // 128
    float* s_sst = s_bb + 128;    // 128
    float* s_ws  = s_sst + 128;   // 8*16
    float* s_tr  = s_ws + 128;    // 8*32*33
    const int tid = threadIdx.x, lane = tid & 31, warp = tid >> 5;
    const int b = blockIdx.y, kb = blockIdx.x;

    for (int i = tid; i < 64 * 32; i += 256) {
        int c = i >> 5, j = i & 31;
        s_wa[i] = w2a[j * 64 + c];
    }
    for (int i = tid; i < 128 * 32; i += 256) s_wb[i] = w2b[i];
    if (tid < 32) s_ba[tid] = b2a[tid];
    if (tid < 128) s_bb[tid] = b2b[tid];
    if (tid < 128) s_sst[tid] = g_ss[(size_t)b * 128 + tid];
    __syncthreads();

    const int k = kb * 8 + warp;
    const size_t base = (size_t)b * NK + k;

    float h[32];
#pragma unroll
    for (int j = 0; j < 32; j++) h[j] = s_ba[j];

#pragma unroll
    for (int i = 0; i < 16; i++) {
        float4 f = g_y1[(base * 16 + i) * NSMP + lane];
        float vv[4] = {f.x, f.y, f.z, f.w};
#pragma unroll
        for (int sub = 0; sub < 4; sub++) {
            int c = i * 4 + sub;
            float xc = fmaxf(fmaf(vv[sub], s_sst[2 * c], s_sst[2 * c + 1]), 0.f);
            const float4* w = (const float4*)&s_wa[c * 32];
#pragma unroll
            for (int q4 = 0; q4 < 8; q4++) {
                float4 ww = w[q4];
                h[q4 * 4 + 0] = fmaf(ww.x, xc, h[q4 * 4 + 0]);
                h[q4 * 4 + 1] = fmaf(ww.y, xc, h[q4 * 4 + 1]);
                h[q4 * 4 + 2] = fmaf(ww.z, xc, h[q4 * 4 + 2]);
                h[q4 * 4 + 3] = fmaf(ww.w, xc, h[q4 * 4 + 3]);
            }
        }
    }

    float s1[8] = {0, 0, 0, 0, 0, 0, 0, 0}, s2[8] = {0, 0, 0, 0, 0, 0, 0, 0};
    float* tr = s_tr + warp * (32 * 33);

    for (int ch = 0; ch < 4; ch++) {
        float yv[32];
#pragma unroll
        for (int i = 0; i < 32; i++) {
            int o = ch * 32 + i;
            const float4* w = (const float4*)&s_wb[o * 32];
            float a = s_bb[o];
#pragma unroll
            for (int q4 = 0; q4 < 8; q4++) {
                float4 ww = w[q4];
                a = fmaf(ww.x, h[q4 * 4 + 0], a);
                a = fmaf(ww.y, h[q4 * 4 + 1], a);
                a = fmaf(ww.z, h[q4 * 4 + 2], a);
                a = fmaf(ww.w, h[q4 * 4 + 3], a);
            }
            yv[i] = a;
            int g = o >> 4;
            s1[g] += a;
            s2[g] = fmaf(a, a, s2[g]);
        }
        __syncwarp();
#pragma unroll
        for (int i = 0; i < 32; i++) tr[lane * 33 + i] = yv[i];
        __syncwarp();
        float mx = tr[lane], mn = mx;
#pragma unroll
        for (int s = 1; s < 32; s++) {
            float v = tr[s * 33 + lane];
            mx = fmaxf(mx, v);
            mn = fminf(mn, v);
        }
        g_mx[base * 128 + ch * 32 + lane] = mx;
        g_mn[base * 128 + ch * 32 + lane] = mn;
        __syncwarp();
    }

#pragma unroll
    for (int g = 0; g < 8; g++) {
#pragma unroll
        for (int o = 16; o > 0; o >>= 1) {
            s1[g] += __shfl_xor_sync(0xffffffffu, s1[g], o);
            s2[g] += __shfl_xor_sync(0xffffffffu, s2[g], o);
        }
    }
    if (lane == 0) {
#pragma unroll
        for (int g = 0; g < 8; g++) {
            s_ws[warp * 16 + 2 * g + 0] = s1[g];
            s_ws[warp * 16 + 2 * g + 1] = s2[g];
        }
    }
    __syncthreads();
    if (tid < 16) {
        float v = 0.f;
        for (int w = 0; w < 8; w++) v += s_ws[w * 16 + tid];
        g_part[((size_t)b * 256 + kb) * 16 + tid] = v;
    }
}

// =========================== Final: apply GN+ReLU to extremum ===========================
__global__ void __launch_bounds__(256) final_kernel(float* __restrict__ out)
{
    int e = blockIdx.x * 256 + threadIdx.x;           // 0 .. B*K*128/4-1
    int c4 = e & 31;
    int bk = e >> 5;
    int b = bk >> 11;
    int c = c4 * 4;
    float4 mx = ((const float4*)g_mx)[e];
    float4 mn = ((const float4*)g_mn)[e];
    const float4* S = (const float4*)&g_ss[((size_t)b * 128 + c) * 2];
    float4 s0 = S[0], s1 = S[1];
    float4 o;
    o.x = fmaxf(fmaf(s0.x, (s0.x >= 0.f ? mx.x : mn.x), s0.y), 0.f);
    o.y = fmaxf(fmaf(s0.z, (s0.z >= 0.f ? mx.y : mn.y), s0.w), 0.f);
    o.z = fmaxf(fmaf(s1.x, (s1.x >= 0.f ? mx.z : mn.z), s1.y), 0.f);
    o.w = fmaxf(fmaf(s1.z, (s1.z >= 0.f ? mx.w : mn.w), s1.w), 0.f);
    ((float4*)(out + (size_t)NB * NK * 3))[e] = o;
}

// =========================== launch ===========================
extern "C" void kernel_launch(void* const* d_in, const int* in_sizes, int n_in,
                              void* d_out, int out_size)
{
    const float* xyz  = (const float*)d_in[0];
    const float* feat = (const float*)d_in[1];
    const float* w0a = (const float*)d_in[2];
    const float* b0a = (const float*)d_in[3];
    const float* w0b = (const float*)d_in[4];
    const float* b0b = (const float*)d_in[5];
    const float* g0  = (const float*)d_in[6];
    const float* be0 = (const float*)d_in[7];
    const float* w1a = (const float*)d_in[8];
    const float* b1a = (const float*)d_in[9];
    const float* w1b = (const float*)d_in[10];
    const float* b1b = (const float*)d_in[11];
    const float* g1  = (const float*)d_in[12];
    const float* be1 = (const float*)d_in[13];
    const float* w2a = (const float*)d_in[14];
    const float* b2a = (const float*)d_in[15];
    const float* w2b = (const float*)d_in[16];
    const float* b2b = (const float*)d_in[17];
    const float* g2  = (const float*)d_in[18];
    const float* be2 = (const float*)d_in[19];
    float* out = (float*)d_out;

    cudaFuncSetAttribute(fps_kernel, cudaFuncAttributeMaxDynamicSharedMemorySize, 131072);
    cudaFuncSetAttribute(knn_kernel, cudaFuncAttributeMaxDynamicSharedMemorySize, 131072);
    cudaFuncSetAttribute(layer2_kernel, cudaFuncAttributeMaxDynamicSharedMemorySize, 65536);

    fps_kernel<<<NB, 512, 131072>>>(xyz, out);
    knn_kernel<<<dim3(32, NB), 256, 131072>>>(xyz, out);
    layer0_kernel<<<dim3(256, NB), 256>>>(xyz, feat, out, w0a, b0a, w0b, b0b);
    finalize_kernel<<<NB, 128>>>(g0, be0, 64);
    layer1_kernel<<<dim3(256, NB), 256>>>(w1a, b1a, w1b, b1b);
    finalize_kernel<<<NB, 128>>>(g1, be1, 64);
    layer2_kernel<<<dim3(256, NB), 256, 61440>>>(w2a, b2a, w2b, b2b);
    finalize_kernel<<<NB, 256>>>(g2, be2, 128);
    final_kernel<<<2048, 256>>>(out);
}